// round 13
// baseline (speedup 1.0000x reference)
#include <cuda_runtime.h>
#include <math.h>

#define TT 20
#define CC 128
#define DM 256
#define NH 16
#define HWP 16384
#define ZROW 132
#define SSTRIDE 2644
#define ASTRIDE 2112

// smem offsets (floats) — 8 samples, tight overlays
#define OFF_Z   0          // raw z; A overlays [0,16896)
#define OFF_PL  16896
#define OFF_PH  18944      // MLP partial quarters 0,1
#define OFF_OB  16896      // reuses PL after phase 6
#define OFF_RS  21152
#define OFF_SC  23264      // COLS overlay pre-P2; scores->attn; PH quarters 2,3 in P6
#define OFF_GS  25824
#define OFF_CR  26080
#define SMEM_FLOATS 26208
#define SMEM_BYTES (SMEM_FLOATS * 4)

__device__ float g_Rp[NH * CC];
__device__ float g_G[NH * NH];
__device__ float g_bR[NH];
__device__ float g_W4[DM * CC];      // [c4][d][j]
__device__ float g_GWT[NH * DM];     // [g][d]
__device__ float g_bW[DM];
__device__ float g_M8[DM * CC];      // [d4][q][k*2+r] : o-pair interleaved
__device__ float g_vconst[2 * TT * DM];
__device__ float g_sconst[2 * TT * NH];

union F2U { float2 f; unsigned long long u; };

__device__ __forceinline__ float2 fma2(float2 a, float2 b, float2 c) {
    F2U ua, ub, uc, ud;
    ua.f = a; ub.f = b; uc.f = c;
    asm("fma.rn.f32x2 %0, %1, %2, %3;"
        : "=l"(ud.u) : "l"(ua.u), "l"(ub.u), "l"(uc.u));
    return ud.f;
}
__device__ __forceinline__ float2 mul2(float2 a, float2 b) {
    F2U ua, ub, ud;
    ua.f = a; ub.f = b;
    asm("mul.rn.f32x2 %0, %1, %2;" : "=l"(ud.u) : "l"(ua.u), "l"(ub.u));
    return ud.f;
}
__device__ __forceinline__ float2 mk2(float a, float b) {
    float2 r; r.x = a; r.y = b; return r;
}

// ---------------------------------------------------------------------------
// Setup (grid 120, 256 thr)
__global__ void ltae_setup(const int* __restrict__ bpos,
                           const float* __restrict__ in_w,
                           const float* __restrict__ in_b,
                           const float* __restrict__ inconv_w,
                           const float* __restrict__ inconv_b,
                           const float* __restrict__ Q,
                           const float* __restrict__ k_w,
                           const float* __restrict__ k_b,
                           const float* __restrict__ mlp_w) {
    __shared__ float sqk[NH * DM];
    __shared__ float srow[2 * DM];
    const int tid = threadIdx.x;
    const int blk = blockIdx.x;

    for (int i = tid; i < NH * DM; i += 256) {
        int h = i >> 8, dm = i & 255;
        float acc = 0.f;
        #pragma unroll
        for (int d = 0; d < 4; d++) acc += Q[h * 4 + d] * k_w[(h * 4 + d) * DM + dm];
        sqk[i] = acc;
    }
    __syncthreads();

    if (blk < 16) {
        const int h = blk;
        if (tid < 128) {
            int c = tid;
            float acc = 0.f;
            for (int dm = 0; dm < DM; dm++)
                acc += sqk[h * DM + dm] * inconv_w[dm * CC + c];
            srow[c] = acc;
            g_Rp[h * CC + c] = in_w[c] * acc;
        }
        __syncthreads();
        if (tid < 16) {
            float acc = 0.f;
            #pragma unroll
            for (int j = 0; j < 8; j++) {
                int c = tid * 8 + j;
                acc += in_w[c] * srow[c];
            }
            g_G[h * 16 + tid] = acc;
        }
        if (tid == 0) {
            float acc = 0.f;
            for (int c = 0; c < CC; c++) acc += in_b[c] * srow[c];
            g_bR[h] = acc;
        }
    } else if (blk < 56) {
        const int bt = blk - 16;
        {
            int dm = tid;
            int ii = dm & 15;
            float ex = (float)(ii & ~1) * (1.0f / 16.0f);
            float denom = exp2f(ex * 9.96578428466209f);   // log2(1000)
            float tab = (float)bpos[bt] / denom;
            float pe = (ii & 1) ? cosf(tab) : sinf(tab);
            float vv = inconv_b[dm] + pe;
            g_vconst[bt * DM + dm] = vv;
            srow[dm] = vv;
        }
        __syncthreads();
        if (tid < 16) {
            int h = tid;
            float acc = 0.f;
            #pragma unroll
            for (int d = 0; d < 4; d++) acc += Q[h * 4 + d] * k_b[h * 4 + d];
            for (int dm = 0; dm < DM; dm++) acc += srow[dm] * sqk[h * DM + dm];
            g_sconst[bt * NH + h] = acc;
        }
    } else if (blk < 88) {
        const int d0 = (blk - 56) * 8;
        for (int k = 0; k < 8; k++) {
            int d = d0 + k;
            if (tid < 128) {
                int c = tid;
                float w = inconv_w[d * CC + c];
                float wp = in_w[c] * w;
                g_W4[(c >> 2) * 1024 + d * 4 + (c & 3)] = wp;
                srow[c] = wp;
                srow[128 + c] = in_b[c] * w;
            }
            __syncthreads();
            if (tid < 16) {
                float acc = 0.f;
                #pragma unroll
                for (int j = 0; j < 8; j++) acc += srow[tid * 8 + j];
                g_GWT[tid * DM + d] = acc;
            }
            if (tid == 0) {
                float acc = 0.f;
                for (int c = 0; c < CC; c++) acc += srow[128 + c];
                g_bW[d] = acc;
            }
            __syncthreads();
        }
    } else {
        // M8 repack: o-pair interleaved. [d4][q][k*2+r] = mlp_w[(2q+r)*DM + d4*4+k]
        const int o0 = (blk - 88) * 4;
        for (int idx = tid; idx < 4 * DM; idx += 256) {
            int oo = o0 + (idx >> 8), dm = idx & 255;
            g_M8[(dm >> 2) * 512 + (oo >> 1) * 8 + (dm & 3) * 2 + (oo & 1)] =
                mlp_w[oo * DM + dm];
        }
    }
}

// ---------------------------------------------------------------------------
// Main: 512 threads, 8 w positions per block, 2 CTAs/SM.
__global__ void __launch_bounds__(512, 2)
ltae_main(const float* __restrict__ x,
          const float* __restrict__ mlp_b,
          const float* __restrict__ ln_w, const float* __restrict__ ln_b,
          const float* __restrict__ on_w, const float* __restrict__ on_b,
          float* __restrict__ out) {
    extern __shared__ float sm[];
    float* Z    = sm + OFF_Z;
    float* PL   = sm + OFF_PL;
    float* PH   = sm + OFF_PH;   // quarters 0,1
    float* OB   = sm + OFF_OB;
    float* RS   = sm + OFF_RS;
    float* SC   = sm + OFF_SC;
    float* PH2  = sm + OFF_SC;   // quarters 2,3 (SC dead after P5)
    float* COLS = sm + OFF_SC;   // overlay, dead before scores written
    float* GS   = sm + OFF_GS;
    float* CR   = sm + OFF_CR;

    const int tid = threadIdx.x;
    const int blk = blockIdx.x;
    const int wblk = blk & 15;
    const int hrow = (blk >> 4) & 127;
    const int b = blk >> 11;
    const int w0 = wblk * 8;

    const float* xb = x + (size_t)b * TT * CC * HWP + (size_t)hrow * 128 + w0;

    // stage Rp (one float4 per thread)
    {
        int h = tid >> 5, c4 = tid & 31;
        *(float4*)&RS[h * ZROW + c4 * 4] =
            *(const float4*)&g_Rp[h * CC + c4 * 4];
    }

    // ---- Phase 1: scalar gather (sector-coalesced over w) + column partials
    const int s = tid & 7;
    const int lane64 = tid >> 3;
    {
        float s0 = 0.f, q0 = 0.f, s1 = 0.f, q1 = 0.f;
        float* zp = Z + s * SSTRIDE;
        #pragma unroll 4
        for (int k = 0; k < 40; k++) {
            int pair = lane64 + (k << 6);
            float val = __ldg(xb + (size_t)pair * HWP + s);
            zp[(pair >> 7) * ZROW + (pair & 127)] = val;
            if (k & 1) { s1 += val; q1 += val * val; }
            else       { s0 += val; q0 += val * val; }
        }
        *(float2*)&COLS[s * 260 + lane64 * 2] = mk2(s0, q0);
        *(float2*)&COLS[s * 260 + (lane64 + 64) * 2] = mk2(s1, q1);
    }
    __syncthreads();

    // ---- stats + CR fused: warp w owns ss {2w, 2w+1}; GS produced and
    //      consumed within the same warp -> __syncwarp suffices.
    if (tid < 128) {
        {
            int ss = tid >> 4, g = tid & 15;
            float sum = 0.f, sq = 0.f;
            #pragma unroll
            for (int j = 0; j < 8; j++) {
                float2 p = *(const float2*)&COLS[ss * 260 + (g * 8 + j) * 2];
                sum += p.x; sq += p.y;
            }
            float mu = sum * (1.f / 160.f);
            float var = sq * (1.f / 160.f) - mu * mu;
            float inv = rsqrtf(var + 1e-5f);
            GS[(ss * 16 + g) * 2]     = inv;
            GS[(ss * 16 + g) * 2 + 1] = mu * inv;
        }
        __syncwarp();
        {
            int ss = tid >> 4, h = tid & 15;
            float c = g_bR[h];
            #pragma unroll
            for (int g = 0; g < 16; g++)
                c -= GS[(ss * 16 + g) * 2 + 1] * g_G[h * 16 + g];
            CR[ss * 16 + h] = c;
        }
    }
    __syncthreads();

    // ---- Phase 2: scores from RAW z, 4t x 4h register tile, inv folded
    if (tid < 160) {
        const int hq = tid & 3;
        const int tmp = tid >> 2;
        const int tq = tmp % 5;
        const int ss = tmp / 5;
        const int t0 = tq * 4;
        const float* zb = Z + ss * SSTRIDE + t0 * ZROW;
        const float* rb = RS + hq * 4 * ZROW;
        float2 acc[4][4];
        #pragma unroll
        for (int tt = 0; tt < 4; tt++)
            #pragma unroll
            for (int j = 0; j < 4; j++) acc[tt][j] = mk2(0.f, 0.f);
        #pragma unroll 4
        for (int c4 = 0; c4 < 32; c4++) {
            float inv = GS[(ss * 16 + (c4 >> 1)) * 2];
            float2 iv = mk2(inv, inv);
            float2 al[4], ah[4];
            #pragma unroll
            for (int tt = 0; tt < 4; tt++) {
                float4 a = *(const float4*)(zb + tt * ZROW + c4 * 4);
                al[tt] = mul2(mk2(a.x, a.y), iv);
                ah[tt] = mul2(mk2(a.z, a.w), iv);
            }
            #pragma unroll
            for (int j = 0; j < 4; j++) {
                float4 r = *(const float4*)(rb + j * ZROW + c4 * 4);
                float2 rl = mk2(r.x, r.y), rh = mk2(r.z, r.w);
                #pragma unroll
                for (int tt = 0; tt < 4; tt++) {
                    acc[tt][j] = fma2(al[tt], rl, acc[tt][j]);
                    acc[tt][j] = fma2(ah[tt], rh, acc[tt][j]);
                }
            }
        }
        #pragma unroll
        for (int tt = 0; tt < 4; tt++)
            #pragma unroll
            for (int j = 0; j < 4; j++) {
                int h = hq * 4 + j, t = t0 + tt;
                SC[ss * 320 + h * 20 + t] =
                    (acc[tt][j].x + acc[tt][j].y + CR[ss * 16 + h]
                     + g_sconst[(b * TT + t) * NH + h]) * 0.5f;
            }
    }
    __syncthreads();

    // ---- Phase 3: softmax + in-place transpose; the (ss) region is owned
    //      entirely by one warp -> __syncwarp covers the WAR hazard.
    if (tid < 128) {
        float att[TT];
        int ss = tid >> 4, h = tid & 15;
        {
            const float* sp = SC + ss * 320 + h * 20;
            float m = -1e30f;
            #pragma unroll
            for (int t = 0; t < TT; t++) m = fmaxf(m, sp[t]);
            float sumv = 0.f;
            #pragma unroll
            for (int t = 0; t < TT; t++) { att[t] = __expf(sp[t] - m); sumv += att[t]; }
            float r = 1.f / sumv;
            #pragma unroll
            for (int t = 0; t < TT; t++) att[t] *= r;
        }
        __syncwarp();
        #pragma unroll
        for (int t = 0; t < TT; t++) SC[ss * 320 + t * 16 + h] = att[t];
    }
    __syncthreads();

    // ---- Phase 4: A[s,h,c] = inv_g * sum_t attn * z_raw, overlay into Z
    //      thread = (ss 8, hh 2, cq 32): z as LDS.128, attn as 2x LDS.128
    {
        const int ss4 = tid >> 6;
        const int hh = (tid >> 5) & 1;
        const int cq = tid & 31;
        float2 acc[8][2];   // [h-in-half][c01, c23]
        #pragma unroll
        for (int hp = 0; hp < 8; hp++) {
            acc[hp][0] = mk2(0.f, 0.f);
            acc[hp][1] = mk2(0.f, 0.f);
        }
        const float* zp = Z + ss4 * SSTRIDE + cq * 4;
        const float* ap = SC + ss4 * 320 + hh * 8;
        #pragma unroll 4
        for (int t = 0; t < TT; t++) {
            float4 z4 = *(const float4*)(zp + t * ZROW);
            float4 A0 = *(const float4*)(ap + t * 16);
            float4 A1 = *(const float4*)(ap + t * 16 + 4);
            float2 z01 = mk2(z4.x, z4.y), z23 = mk2(z4.z, z4.w);
            float av[8] = {A0.x, A0.y, A0.z, A0.w, A1.x, A1.y, A1.z, A1.w};
            #pragma unroll
            for (int hp = 0; hp < 8; hp++) {
                float2 a2 = mk2(av[hp], av[hp]);
                acc[hp][0] = fma2(a2, z01, acc[hp][0]);
                acc[hp][1] = fma2(a2, z23, acc[hp][1]);
            }
        }
        float inv = GS[(ss4 * 16 + (cq >> 1)) * 2];
        float2 iv = mk2(inv, inv);
        __syncthreads();              // all raw-z reads complete before overlay
        #pragma unroll
        for (int hp = 0; hp < 8; hp++) {
            float2 a01 = mul2(acc[hp][0], iv);
            float2 a23 = mul2(acc[hp][1], iv);
            float4 w;
            w.x = a01.x; w.y = a01.y; w.z = a23.x; w.w = a23.y;
            *(float4*)(Z + ss4 * ASTRIDE + (hh * 8 + hp) * ZROW + cq * 4) = w;
        }
    }
    __syncthreads();

    // ---- Phase 5: pooled; 256 threads own d, single pass over 8 samples
    if (tid < 256) {
        const int d = tid;
        const int h = d >> 4;
        float2 acc2[8];
        #pragma unroll
        for (int j = 0; j < 8; j++) acc2[j] = mk2(0.f, 0.f);
        #pragma unroll 4
        for (int c4 = 0; c4 < 32; c4++) {
            float4 w = __ldg((const float4*)(g_W4 + c4 * 1024 + d * 4));
            float2 wl = mk2(w.x, w.y), wh = mk2(w.z, w.w);
            #pragma unroll
            for (int j = 0; j < 8; j++) {
                float4 a = *(const float4*)(Z + j * ASTRIDE + h * ZROW + c4 * 4);
                acc2[j] = fma2(mk2(a.x, a.y), wl, acc2[j]);
                acc2[j] = fma2(mk2(a.z, a.w), wh, acc2[j]);
            }
        }
        float p[8];
        float bw = __ldg(g_bW + d);
        #pragma unroll
        for (int j = 0; j < 8; j++) p[j] = acc2[j].x + acc2[j].y + bw;
        #pragma unroll
        for (int g = 0; g < 16; g++) {
            float gw = __ldg(g_GWT + g * 256 + d);
            #pragma unroll
            for (int j = 0; j < 8; j++)
                p[j] -= GS[(j * 16 + g) * 2 + 1] * gw;
        }
        const float* vc = g_vconst + b * TT * DM + d;
        #pragma unroll 4
        for (int t = 0; t < TT; t++) {
            float vv = __ldg(vc + t * DM);
            #pragma unroll
            for (int j = 0; j < 8; j++)
                p[j] += SC[j * 320 + t * 16 + h] * vv;
        }
        #pragma unroll
        for (int j = 0; j < 8; j++) PL[j * 256 + d] = p[j];
    }
    __syncthreads();

    // ---- Phase 6: MLP; 256 threads = (q 64 o-pairs, dq 4 d-quarters)
    if (tid < 256) {
        const int q = tid & 63;
        const int dq = tid >> 6;
        float2 acc[8];
        #pragma unroll
        for (int j = 0; j < 8; j++) acc[j] = mk2(0.f, 0.f);
        const int d4base = dq * 16;
        #pragma unroll 4
        for (int k = 0; k < 16; k++) {
            int d4 = d4base + k;
            float4 w0 = __ldg((const float4*)(g_M8 + d4 * 512 + q * 8));
            float4 w1 = __ldg((const float4*)(g_M8 + d4 * 512 + q * 8 + 4));
            #pragma unroll
            for (int j = 0; j < 8; j++) {
                float4 pq = *(const float4*)(PL + j * 256 + d4 * 4);
                acc[j] = fma2(mk2(pq.x, pq.x), mk2(w0.x, w0.y), acc[j]);
                acc[j] = fma2(mk2(pq.y, pq.y), mk2(w0.z, w0.w), acc[j]);
                acc[j] = fma2(mk2(pq.z, pq.z), mk2(w1.x, w1.y), acc[j]);
                acc[j] = fma2(mk2(pq.w, pq.w), mk2(w1.z, w1.w), acc[j]);
            }
        }
        float* phq = (dq < 2) ? (PH + dq * 1024) : (PH2 + (dq - 2) * 1024);
        #pragma unroll
        for (int j = 0; j < 8; j++)
            *(float2*)(phq + j * 128 + q * 2) = acc[j];
    }
    __syncthreads();

    // ---- Phase 7: combine 4 quarters + LN + GELU + GN + transpose (256 thr)
    if (tid < 256) {
        int ss = tid >> 5, lane = tid & 31;
        float4 a0 = *(const float4*)(PH + ss * 128 + lane * 4);
        float4 a1 = *(const float4*)(PH + 1024 + ss * 128 + lane * 4);
        float4 a2 = *(const float4*)(PH2 + ss * 128 + lane * 4);
        float4 a3 = *(const float4*)(PH2 + 1024 + ss * 128 + lane * 4);
        float4 bb = __ldg((const float4*)(mlp_b + lane * 4));
        float4 vq;
        vq.x = a0.x + a1.x + a2.x + a3.x + bb.x;
        vq.y = a0.y + a1.y + a2.y + a3.y + bb.y;
        vq.z = a0.z + a1.z + a2.z + a3.z + bb.z;
        vq.w = a0.w + a1.w + a2.w + a3.w + bb.w;
        float smv = vq.x + vq.y + vq.z + vq.w;
        float sqv = vq.x * vq.x + vq.y * vq.y + vq.z * vq.z + vq.w * vq.w;
        #pragma unroll
        for (int off = 16; off; off >>= 1) {
            smv += __shfl_xor_sync(0xffffffffu, smv, off);
            sqv += __shfl_xor_sync(0xffffffffu, sqv, off);
        }
        float mu = smv * (1.f / 128.f);
        float inv = rsqrtf(sqv * (1.f / 128.f) - mu * mu + 1e-5f);
        float g[4]; float vv[4] = {vq.x, vq.y, vq.z, vq.w};
        #pragma unroll
        for (int j = 0; j < 4; j++) {
            int o = lane * 4 + j;
            float u = (vv[j] - mu) * inv * ln_w[o] + ln_b[o];
            g[j] = 0.5f * u * (1.f + erff(u * 0.70710678118654752f));
        }
        float s4v = g[0] + g[1] + g[2] + g[3];
        float q4 = g[0] * g[0] + g[1] * g[1] + g[2] * g[2] + g[3] * g[3];
        float s8 = s4v + __shfl_xor_sync(0xffffffffu, s4v, 1);
        float q8 = q4 + __shfl_xor_sync(0xffffffffu, q4, 1);
        float mu2 = s8 * 0.125f;
        float inv2 = rsqrtf(q8 * 0.125f - mu2 * mu2 + 1e-5f);
        #pragma unroll
        for (int j = 0; j < 4; j++) {
            int o = lane * 4 + j;
            OB[o * 9 + ss] = (g[j] - mu2) * inv2 * on_w[o] + on_b[o];
        }
    }
    __syncthreads();

    // ---- coalesced store: 8*128 floats
    #pragma unroll
    for (int k = tid; k < 1024; k += 512) {
        int o = k >> 3, sw = k & 7;
        out[(((size_t)(b * 128 + o)) << 14) + hrow * 128 + w0 + sw] = OB[o * 9 + sw];
    }
}

// ---------------------------------------------------------------------------
extern "C" void kernel_launch(void* const* d_in, const int* in_sizes, int n_in,
                              void* d_out, int out_size) {
    const float* x        = (const float*)d_in[0];
    const int*   bpos     = (const int*)  d_in[1];
    const float* in_w     = (const float*)d_in[2];
    const float* in_b     = (const float*)d_in[3];
    const float* inconv_w = (const float*)d_in[4];
    const float* inconv_b = (const float*)d_in[5];
    const float* Q        = (const float*)d_in[6];
    const float* k_w      = (const float*)d_in[7];
    const float* k_b      = (const float*)d_in[8];
    const float* mlp_w    = (const float*)d_in[9];
    const float* mlp_b    = (const float*)d_in[10];
    const float* ln_w     = (const float*)d_in[11];
    const float* ln_b     = (const float*)d_in[12];
    const float* on_w     = (const float*)d_in[13];
    const float* on_b     = (const float*)d_in[14];
    float* out = (float*)d_out;

    cudaFuncSetAttribute(ltae_main, cudaFuncAttributeMaxDynamicSharedMemorySize,
                         SMEM_BYTES);

    ltae_setup<<<120, 256>>>(bpos, in_w, in_b, inconv_w, inconv_b, Q, k_w, k_b,
                             mlp_w);
    ltae_main<<<4096, 512, SMEM_BYTES>>>(x, mlp_b, ln_w, ln_b, on_w, on_b, out);
}

// round 14
// speedup vs baseline: 1.0450x; 1.0450x over previous
#include <cuda_runtime.h>
#include <math.h>

#define TT 20
#define CC 128
#define DM 256
#define NH 16
#define HWP 16384
#define ZROW 132
#define SSTRIDE 2644
#define ASTRIDE 2112

// smem offsets (floats) — 8 samples, tight overlays
#define OFF_Z   0          // raw z; A overlays [0,16896)
#define OFF_PL  16896
#define OFF_PH  18944      // MLP partial quarters 0,1
#define OFF_OB  16896      // reuses PL after phase 6
#define OFF_RS  21152
#define OFF_SC  23264      // COLS overlay pre-P2; scores->attn; PH quarters 2,3 in P6
#define OFF_GS  25824
#define OFF_CR  26080
#define SMEM_FLOATS 26208
#define SMEM_BYTES (SMEM_FLOATS * 4)

__device__ float g_Rp[NH * CC];
__device__ float g_G[NH * NH];
__device__ float g_bR[NH];
__device__ float g_W4[DM * CC];      // [c4][d][j]
__device__ float g_GWT[NH * DM];     // [g][d]
__device__ float g_bW[DM];
__device__ float g_M8[DM * CC];      // [d4][q][k*2+r] : o-pair interleaved
__device__ float g_vconst[2 * TT * DM];
__device__ float g_sconst[2 * TT * NH];

union F2U { float2 f; unsigned long long u; };

__device__ __forceinline__ float2 fma2(float2 a, float2 b, float2 c) {
    F2U ua, ub, uc, ud;
    ua.f = a; ub.f = b; uc.f = c;
    asm("fma.rn.f32x2 %0, %1, %2, %3;"
        : "=l"(ud.u) : "l"(ua.u), "l"(ub.u), "l"(uc.u));
    return ud.f;
}
__device__ __forceinline__ float2 mul2(float2 a, float2 b) {
    F2U ua, ub, ud;
    ua.f = a; ub.f = b;
    asm("mul.rn.f32x2 %0, %1, %2;" : "=l"(ud.u) : "l"(ua.u), "l"(ub.u));
    return ud.f;
}
__device__ __forceinline__ float2 mk2(float a, float b) {
    float2 r; r.x = a; r.y = b; return r;
}

// ---------------------------------------------------------------------------
// Setup (grid 120, 256 thr)
__global__ void ltae_setup(const int* __restrict__ bpos,
                           const float* __restrict__ in_w,
                           const float* __restrict__ in_b,
                           const float* __restrict__ inconv_w,
                           const float* __restrict__ inconv_b,
                           const float* __restrict__ Q,
                           const float* __restrict__ k_w,
                           const float* __restrict__ k_b,
                           const float* __restrict__ mlp_w) {
    __shared__ float sqk[NH * DM];
    __shared__ float srow[2 * DM];
    const int tid = threadIdx.x;
    const int blk = blockIdx.x;

    for (int i = tid; i < NH * DM; i += 256) {
        int h = i >> 8, dm = i & 255;
        float acc = 0.f;
        #pragma unroll
        for (int d = 0; d < 4; d++) acc += Q[h * 4 + d] * k_w[(h * 4 + d) * DM + dm];
        sqk[i] = acc;
    }
    __syncthreads();

    if (blk < 16) {
        const int h = blk;
        if (tid < 128) {
            int c = tid;
            float acc = 0.f;
            for (int dm = 0; dm < DM; dm++)
                acc += sqk[h * DM + dm] * inconv_w[dm * CC + c];
            srow[c] = acc;
            g_Rp[h * CC + c] = in_w[c] * acc;
        }
        __syncthreads();
        if (tid < 16) {
            float acc = 0.f;
            #pragma unroll
            for (int j = 0; j < 8; j++) {
                int c = tid * 8 + j;
                acc += in_w[c] * srow[c];
            }
            g_G[h * 16 + tid] = acc;
        }
        if (tid == 0) {
            float acc = 0.f;
            for (int c = 0; c < CC; c++) acc += in_b[c] * srow[c];
            g_bR[h] = acc;
        }
    } else if (blk < 56) {
        const int bt = blk - 16;
        {
            int dm = tid;
            int ii = dm & 15;
            // denom = 1000^( (2*(ii/2)) / 16 )  computed in f32 (MUFU path)
            float ex = (float)(ii & ~1) * (1.0f / 16.0f);
            float denom = exp2f(ex * 9.96578428466209f);   // log2(1000)
            float tab = (float)bpos[bt] / denom;
            float pe = (ii & 1) ? cosf(tab) : sinf(tab);
            float vv = inconv_b[dm] + pe;
            g_vconst[bt * DM + dm] = vv;
            srow[dm] = vv;
        }
        __syncthreads();
        if (tid < 16) {
            int h = tid;
            float acc = 0.f;
            #pragma unroll
            for (int d = 0; d < 4; d++) acc += Q[h * 4 + d] * k_b[h * 4 + d];
            for (int dm = 0; dm < DM; dm++) acc += srow[dm] * sqk[h * DM + dm];
            g_sconst[bt * NH + h] = acc;
        }
    } else if (blk < 88) {
        const int d0 = (blk - 56) * 8;
        for (int k = 0; k < 8; k++) {
            int d = d0 + k;
            if (tid < 128) {
                int c = tid;
                float w = inconv_w[d * CC + c];
                float wp = in_w[c] * w;
                g_W4[(c >> 2) * 1024 + d * 4 + (c & 3)] = wp;
                srow[c] = wp;
                srow[128 + c] = in_b[c] * w;
            }
            __syncthreads();
            if (tid < 16) {
                float acc = 0.f;
                #pragma unroll
                for (int j = 0; j < 8; j++) acc += srow[tid * 8 + j];
                g_GWT[tid * DM + d] = acc;
            }
            if (tid == 0) {
                float acc = 0.f;
                for (int c = 0; c < CC; c++) acc += srow[128 + c];
                g_bW[d] = acc;
            }
            __syncthreads();
        }
    } else {
        // M8 repack: o-pair interleaved. [d4][q][k*2+r] = mlp_w[(2q+r)*DM + d4*4+k]
        const int o0 = (blk - 88) * 4;
        for (int idx = tid; idx < 4 * DM; idx += 256) {
            int oo = o0 + (idx >> 8), dm = idx & 255;
            g_M8[(dm >> 2) * 512 + (oo >> 1) * 8 + (dm & 3) * 2 + (oo & 1)] =
                mlp_w[oo * DM + dm];
        }
    }
}

// ---------------------------------------------------------------------------
// Main: 512 threads, 8 w positions per block, 2 CTAs/SM.
__global__ void __launch_bounds__(512, 2)
ltae_main(const float* __restrict__ x,
          const float* __restrict__ mlp_b,
          const float* __restrict__ ln_w, const float* __restrict__ ln_b,
          const float* __restrict__ on_w, const float* __restrict__ on_b,
          float* __restrict__ out) {
    extern __shared__ float sm[];
    float* Z    = sm + OFF_Z;
    float* PL   = sm + OFF_PL;
    float* PH   = sm + OFF_PH;   // quarters 0,1
    float* OB   = sm + OFF_OB;
    float* RS   = sm + OFF_RS;
    float* SC   = sm + OFF_SC;
    float* PH2  = sm + OFF_SC;   // quarters 2,3 (SC dead after P5)
    float* COLS = sm + OFF_SC;   // overlay, dead before scores written
    float* GS   = sm + OFF_GS;
    float* CR   = sm + OFF_CR;

    const int tid = threadIdx.x;
    const int blk = blockIdx.x;
    const int wblk = blk & 15;
    const int hrow = (blk >> 4) & 127;
    const int b = blk >> 11;
    const int w0 = wblk * 8;

    const float* xb = x + (size_t)b * TT * CC * HWP + (size_t)hrow * 128 + w0;

    // stage Rp (one float4 per thread)
    {
        int h = tid >> 5, c4 = tid & 31;
        *(float4*)&RS[h * ZROW + c4 * 4] =
            *(const float4*)&g_Rp[h * CC + c4 * 4];
    }

    // ---- Phase 1: scalar gather (sector-coalesced over w) + column partials
    const int s = tid & 7;
    const int lane64 = tid >> 3;
    {
        float s0 = 0.f, q0 = 0.f, s1 = 0.f, q1 = 0.f;
        float* zp = Z + s * SSTRIDE;
        #pragma unroll 4
        for (int k = 0; k < 40; k++) {
            int pair = lane64 + (k << 6);
            float val = __ldg(xb + (size_t)pair * HWP + s);
            zp[(pair >> 7) * ZROW + (pair & 127)] = val;
            if (k & 1) { s1 += val; q1 += val * val; }
            else       { s0 += val; q0 += val * val; }
        }
        *(float2*)&COLS[s * 260 + lane64 * 2] = mk2(s0, q0);
        *(float2*)&COLS[s * 260 + (lane64 + 64) * 2] = mk2(s1, q1);
    }
    __syncthreads();

    if (tid < 128) {
        int ss = tid >> 4, g = tid & 15;
        float sum = 0.f, sq = 0.f;
        #pragma unroll
        for (int j = 0; j < 8; j++) {
            float2 p = *(const float2*)&COLS[ss * 260 + (g * 8 + j) * 2];
            sum += p.x; sq += p.y;
        }
        float mu = sum * (1.f / 160.f);
        float var = sq * (1.f / 160.f) - mu * mu;
        float inv = rsqrtf(var + 1e-5f);
        GS[(ss * 16 + g) * 2]     = inv;
        GS[(ss * 16 + g) * 2 + 1] = mu * inv;
    }
    __syncthreads();

    if (tid < 128) {
        int ss = tid >> 4, h = tid & 15;
        float c = g_bR[h];
        #pragma unroll
        for (int g = 0; g < 16; g++)
            c -= GS[(ss * 16 + g) * 2 + 1] * g_G[h * 16 + g];
        CR[ss * 16 + h] = c;
    }
    __syncthreads();

    // ---- Phase 2: scores from RAW z, 4t x 4h register tile, inv folded
    if (tid < 160) {
        const int hq = tid & 3;
        const int tmp = tid >> 2;
        const int tq = tmp % 5;
        const int ss = tmp / 5;
        const int t0 = tq * 4;
        const float* zb = Z + ss * SSTRIDE + t0 * ZROW;
        const float* rb = RS + hq * 4 * ZROW;
        float2 acc[4][4];
        #pragma unroll
        for (int tt = 0; tt < 4; tt++)
            #pragma unroll
            for (int j = 0; j < 4; j++) acc[tt][j] = mk2(0.f, 0.f);
        #pragma unroll 4
        for (int c4 = 0; c4 < 32; c4++) {
            float inv = GS[(ss * 16 + (c4 >> 1)) * 2];
            float2 iv = mk2(inv, inv);
            float2 al[4], ah[4];
            #pragma unroll
            for (int tt = 0; tt < 4; tt++) {
                float4 a = *(const float4*)(zb + tt * ZROW + c4 * 4);
                al[tt] = mul2(mk2(a.x, a.y), iv);
                ah[tt] = mul2(mk2(a.z, a.w), iv);
            }
            #pragma unroll
            for (int j = 0; j < 4; j++) {
                float4 r = *(const float4*)(rb + j * ZROW + c4 * 4);
                float2 rl = mk2(r.x, r.y), rh = mk2(r.z, r.w);
                #pragma unroll
                for (int tt = 0; tt < 4; tt++) {
                    acc[tt][j] = fma2(al[tt], rl, acc[tt][j]);
                    acc[tt][j] = fma2(ah[tt], rh, acc[tt][j]);
                }
            }
        }
        #pragma unroll
        for (int tt = 0; tt < 4; tt++)
            #pragma unroll
            for (int j = 0; j < 4; j++) {
                int h = hq * 4 + j, t = t0 + tt;
                SC[ss * 320 + h * 20 + t] =
                    (acc[tt][j].x + acc[tt][j].y + CR[ss * 16 + h]
                     + g_sconst[(b * TT + t) * NH + h]) * 0.5f;
            }
    }
    __syncthreads();

    // ---- Phase 3: softmax with in-place transpose SC -> attn[s][t][h]
    {
        float att[TT];
        int ss = tid >> 4, h = tid & 15;
        if (tid < 128) {
            const float* sp = SC + ss * 320 + h * 20;
            float m = -1e30f;
            #pragma unroll
            for (int t = 0; t < TT; t++) m = fmaxf(m, sp[t]);
            float sumv = 0.f;
            #pragma unroll
            for (int t = 0; t < TT; t++) { att[t] = __expf(sp[t] - m); sumv += att[t]; }
            float r = 1.f / sumv;
            #pragma unroll
            for (int t = 0; t < TT; t++) att[t] *= r;
        }
        __syncthreads();
        if (tid < 128) {
            #pragma unroll
            for (int t = 0; t < TT; t++) SC[ss * 320 + t * 16 + h] = att[t];
        }
    }
    __syncthreads();

    // ---- Phase 4: A[s,h,c] = inv_g * sum_t attn * z_raw, overlay into Z
    //      thread = (ss 8, hh 2, cq 32): z as LDS.128, attn as 2x LDS.128
    {
        const int ss4 = tid >> 6;
        const int hh = (tid >> 5) & 1;
        const int cq = tid & 31;
        float2 acc[8][2];   // [h-in-half][c01, c23]
        #pragma unroll
        for (int hp = 0; hp < 8; hp++) {
            acc[hp][0] = mk2(0.f, 0.f);
            acc[hp][1] = mk2(0.f, 0.f);
        }
        const float* zp = Z + ss4 * SSTRIDE + cq * 4;
        const float* ap = SC + ss4 * 320 + hh * 8;
        #pragma unroll 4
        for (int t = 0; t < TT; t++) {
            float4 z4 = *(const float4*)(zp + t * ZROW);
            float4 A0 = *(const float4*)(ap + t * 16);
            float4 A1 = *(const float4*)(ap + t * 16 + 4);
            float2 z01 = mk2(z4.x, z4.y), z23 = mk2(z4.z, z4.w);
            float av[8] = {A0.x, A0.y, A0.z, A0.w, A1.x, A1.y, A1.z, A1.w};
            #pragma unroll
            for (int hp = 0; hp < 8; hp++) {
                float2 a2 = mk2(av[hp], av[hp]);
                acc[hp][0] = fma2(a2, z01, acc[hp][0]);
                acc[hp][1] = fma2(a2, z23, acc[hp][1]);
            }
        }
        float inv = GS[(ss4 * 16 + (cq >> 1)) * 2];
        float2 iv = mk2(inv, inv);
        __syncthreads();              // all raw-z reads complete before overlay
        #pragma unroll
        for (int hp = 0; hp < 8; hp++) {
            float2 a01 = mul2(acc[hp][0], iv);
            float2 a23 = mul2(acc[hp][1], iv);
            float4 w;
            w.x = a01.x; w.y = a01.y; w.z = a23.x; w.w = a23.y;
            *(float4*)(Z + ss4 * ASTRIDE + (hh * 8 + hp) * ZROW + cq * 4) = w;
        }
    }
    __syncthreads();

    // ---- Phase 5: pooled; 256 threads own d, single pass over 8 samples
    if (tid < 256) {
        const int d = tid;
        const int h = d >> 4;
        float2 acc2[8];
        #pragma unroll
        for (int j = 0; j < 8; j++) acc2[j] = mk2(0.f, 0.f);
        #pragma unroll 4
        for (int c4 = 0; c4 < 32; c4++) {
            float4 w = __ldg((const float4*)(g_W4 + c4 * 1024 + d * 4));
            float2 wl = mk2(w.x, w.y), wh = mk2(w.z, w.w);
            #pragma unroll
            for (int j = 0; j < 8; j++) {
                float4 a = *(const float4*)(Z + j * ASTRIDE + h * ZROW + c4 * 4);
                acc2[j] = fma2(mk2(a.x, a.y), wl, acc2[j]);
                acc2[j] = fma2(mk2(a.z, a.w), wh, acc2[j]);
            }
        }
        float p[8];
        float bw = __ldg(g_bW + d);
        #pragma unroll
        for (int j = 0; j < 8; j++) p[j] = acc2[j].x + acc2[j].y + bw;
        #pragma unroll
        for (int g = 0; g < 16; g++) {
            float gw = __ldg(g_GWT + g * 256 + d);
            #pragma unroll
            for (int j = 0; j < 8; j++)
                p[j] -= GS[(j * 16 + g) * 2 + 1] * gw;
        }
        const float* vc = g_vconst + b * TT * DM + d;
        #pragma unroll 4
        for (int t = 0; t < TT; t++) {
            float vv = __ldg(vc + t * DM);
            #pragma unroll
            for (int j = 0; j < 8; j++)
                p[j] += SC[j * 320 + t * 16 + h] * vv;
        }
        #pragma unroll
        for (int j = 0; j < 8; j++) PL[j * 256 + d] = p[j];
    }
    __syncthreads();

    // ---- Phase 6: MLP; 256 threads = (q 64 o-pairs, dq 4 d-quarters)
    if (tid < 256) {
        const int q = tid & 63;
        const int dq = tid >> 6;
        float2 acc[8];
        #pragma unroll
        for (int j = 0; j < 8; j++) acc[j] = mk2(0.f, 0.f);
        const int d4base = dq * 16;
        #pragma unroll 4
        for (int k = 0; k < 16; k++) {
            int d4 = d4base + k;
            float4 w0 = __ldg((const float4*)(g_M8 + d4 * 512 + q * 8));
            float4 w1 = __ldg((const float4*)(g_M8 + d4 * 512 + q * 8 + 4));
            #pragma unroll
            for (int j = 0; j < 8; j++) {
                float4 pq = *(const float4*)(PL + j * 256 + d4 * 4);
                acc[j] = fma2(mk2(pq.x, pq.x), mk2(w0.x, w0.y), acc[j]);
                acc[j] = fma2(mk2(pq.y, pq.y), mk2(w0.z, w0.w), acc[j]);
                acc[j] = fma2(mk2(pq.z, pq.z), mk2(w1.x, w1.y), acc[j]);
                acc[j] = fma2(mk2(pq.w, pq.w), mk2(w1.z, w1.w), acc[j]);
            }
        }
        float* phq = (dq < 2) ? (PH + dq * 1024) : (PH2 + (dq - 2) * 1024);
        #pragma unroll
        for (int j = 0; j < 8; j++)
            *(float2*)(phq + j * 128 + q * 2) = acc[j];
    }
    __syncthreads();

    // ---- Phase 7: combine 4 quarters + LN + GELU + GN + transpose (256 thr)
    if (tid < 256) {
        int ss = tid >> 5, lane = tid & 31;
        float4 a0 = *(const float4*)(PH + ss * 128 + lane * 4);
        float4 a1 = *(const float4*)(PH + 1024 + ss * 128 + lane * 4);
        float4 a2 = *(const float4*)(PH2 + ss * 128 + lane * 4);
        float4 a3 = *(const float4*)(PH2 + 1024 + ss * 128 + lane * 4);
        float4 bb = __ldg((const float4*)(mlp_b + lane * 4));
        float4 vq;
        vq.x = a0.x + a1.x + a2.x + a3.x + bb.x;
        vq.y = a0.y + a1.y + a2.y + a3.y + bb.y;
        vq.z = a0.z + a1.z + a2.z + a3.z + bb.z;
        vq.w = a0.w + a1.w + a2.w + a3.w + bb.w;
        float smv = vq.x + vq.y + vq.z + vq.w;
        float sqv = vq.x * vq.x + vq.y * vq.y + vq.z * vq.z + vq.w * vq.w;
        #pragma unroll
        for (int off = 16; off; off >>= 1) {
            smv += __shfl_xor_sync(0xffffffffu, smv, off);
            sqv += __shfl_xor_sync(0xffffffffu, sqv, off);
        }
        float mu = smv * (1.f / 128.f);
        float inv = rsqrtf(sqv * (1.f / 128.f) - mu * mu + 1e-5f);
        float g[4]; float vv[4] = {vq.x, vq.y, vq.z, vq.w};
        #pragma unroll
        for (int j = 0; j < 4; j++) {
            int o = lane * 4 + j;
            float u = (vv[j] - mu) * inv * ln_w[o] + ln_b[o];
            g[j] = 0.5f * u * (1.f + erff(u * 0.70710678118654752f));
        }
        float s4v = g[0] + g[1] + g[2] + g[3];
        float q4 = g[0] * g[0] + g[1] * g[1] + g[2] * g[2] + g[3] * g[3];
        float s8 = s4v + __shfl_xor_sync(0xffffffffu, s4v, 1);
        float q8 = q4 + __shfl_xor_sync(0xffffffffu, q4, 1);
        float mu2 = s8 * 0.125f;
        float inv2 = rsqrtf(q8 * 0.125f - mu2 * mu2 + 1e-5f);
        #pragma unroll
        for (int j = 0; j < 4; j++) {
            int o = lane * 4 + j;
            OB[o * 9 + ss] = (g[j] - mu2) * inv2 * on_w[o] + on_b[o];
        }
    }
    __syncthreads();

    // ---- coalesced store: 8*128 floats
    #pragma unroll
    for (int k = tid; k < 1024; k += 512) {
        int o = k >> 3, sw = k & 7;
        out[(((size_t)(b * 128 + o)) << 14) + hrow * 128 + w0 + sw] = OB[o * 9 + sw];
    }
}

// ---------------------------------------------------------------------------
extern "C" void kernel_launch(void* const* d_in, const int* in_sizes, int n_in,
                              void* d_out, int out_size) {
    const float* x        = (const float*)d_in[0];
    const int*   bpos     = (const int*)  d_in[1];
    const float* in_w     = (const float*)d_in[2];
    const float* in_b     = (const float*)d_in[3];
    const float* inconv_w = (const float*)d_in[4];
    const float* inconv_b = (const float*)d_in[5];
    const float* Q        = (const float*)d_in[6];
    const float* k_w      = (const float*)d_in[7];
    const float* k_b      = (const float*)d_in[8];
    const float* mlp_w    = (const float*)d_in[9];
    const float* mlp_b    = (const float*)d_in[10];
    const float* ln_w     = (const float*)d_in[11];
    const float* ln_b     = (const float*)d_in[12];
    const float* on_w     = (const float*)d_in[13];
    const float* on_b     = (const float*)d_in[14];
    float* out = (float*)d_out;

    cudaFuncSetAttribute(ltae_main, cudaFuncAttributeMaxDynamicSharedMemorySize,
                         SMEM_BYTES);

    ltae_setup<<<120, 256>>>(bpos, in_w, in_b, inconv_w, inconv_b, Q, k_w, k_b,
                             mlp_w);
    ltae_main<<<4096, 512, SMEM_BYTES>>>(x, mlp_b, ln_w, ln_b, on_w, on_b, out);
}

// round 15
// speedup vs baseline: 1.0654x; 1.0195x over previous
#include <cuda_runtime.h>
#include <math.h>

#define TT 20
#define CC 128
#define DM 256
#define NH 16
#define HWP 16384
#define ZROW 132
#define SSTRIDE 2644
#define ASTRIDE 2112

// smem offsets (floats) — 8 samples, tight overlays
#define OFF_Z   0          // raw z; A overlays [0,16896)
#define OFF_PL  16896
#define OFF_PH  18944      // MLP partial quarters 0,1
#define OFF_OB  16896      // reuses PL after phase 6
#define OFF_RS  21152
#define OFF_SC  23264      // COLS overlay pre-P2; scores->attn; PH quarters 2,3 in P6
#define OFF_GS  25824
#define OFF_CR  26080
#define SMEM_FLOATS 26208
#define SMEM_BYTES (SMEM_FLOATS * 4)

__device__ float g_Rp[NH * CC];
__device__ float g_G[NH * NH];
__device__ float g_bR[NH];
__device__ float g_W4[DM * CC];      // [c4][d][j]
__device__ float g_GWT[NH * DM];     // [g][d]
__device__ float g_bW[DM];
__device__ float g_M8[DM * CC];      // [d4][q][k*2+r] : o-pair interleaved
__device__ float g_vconst[2 * TT * DM];
__device__ float g_sconst[2 * TT * NH];

union F2U { float2 f; unsigned long long u; };

__device__ __forceinline__ float2 fma2(float2 a, float2 b, float2 c) {
    F2U ua, ub, uc, ud;
    ua.f = a; ub.f = b; uc.f = c;
    asm("fma.rn.f32x2 %0, %1, %2, %3;"
        : "=l"(ud.u) : "l"(ua.u), "l"(ub.u), "l"(uc.u));
    return ud.f;
}
__device__ __forceinline__ float2 mul2(float2 a, float2 b) {
    F2U ua, ub, ud;
    ua.f = a; ub.f = b;
    asm("mul.rn.f32x2 %0, %1, %2;" : "=l"(ud.u) : "l"(ua.u), "l"(ub.u));
    return ud.f;
}
__device__ __forceinline__ float2 mk2(float a, float b) {
    float2 r; r.x = a; r.y = b; return r;
}

// ---------------------------------------------------------------------------
// Setup (grid 120, 256 thr)
__global__ void ltae_setup(const int* __restrict__ bpos,
                           const float* __restrict__ in_w,
                           const float* __restrict__ in_b,
                           const float* __restrict__ inconv_w,
                           const float* __restrict__ inconv_b,
                           const float* __restrict__ Q,
                           const float* __restrict__ k_w,
                           const float* __restrict__ k_b,
                           const float* __restrict__ mlp_w) {
    __shared__ float sqk[NH * DM];
    __shared__ float srow[2 * DM];
    const int tid = threadIdx.x;
    const int blk = blockIdx.x;

    for (int i = tid; i < NH * DM; i += 256) {
        int h = i >> 8, dm = i & 255;
        float acc = 0.f;
        #pragma unroll
        for (int d = 0; d < 4; d++) acc += Q[h * 4 + d] * k_w[(h * 4 + d) * DM + dm];
        sqk[i] = acc;
    }
    __syncthreads();

    if (blk < 16) {
        const int h = blk;
        if (tid < 128) {
            int c = tid;
            float acc = 0.f;
            for (int dm = 0; dm < DM; dm++)
                acc += sqk[h * DM + dm] * inconv_w[dm * CC + c];
            srow[c] = acc;
            g_Rp[h * CC + c] = in_w[c] * acc;
        }
        __syncthreads();
        if (tid < 16) {
            float acc = 0.f;
            #pragma unroll
            for (int j = 0; j < 8; j++) {
                int c = tid * 8 + j;
                acc += in_w[c] * srow[c];
            }
            g_G[h * 16 + tid] = acc;
        }
        if (tid == 0) {
            float acc = 0.f;
            for (int c = 0; c < CC; c++) acc += in_b[c] * srow[c];
            g_bR[h] = acc;
        }
    } else if (blk < 56) {
        const int bt = blk - 16;
        {
            int dm = tid;
            int ii = dm & 15;
            // denom = 1000^( (2*(ii/2)) / 16 )  computed in f32 (MUFU path)
            float ex = (float)(ii & ~1) * (1.0f / 16.0f);
            float denom = exp2f(ex * 9.96578428466209f);   // log2(1000)
            float tab = (float)bpos[bt] / denom;
            float pe = (ii & 1) ? cosf(tab) : sinf(tab);
            float vv = inconv_b[dm] + pe;
            g_vconst[bt * DM + dm] = vv;
            srow[dm] = vv;
        }
        __syncthreads();
        if (tid < 16) {
            int h = tid;
            float acc = 0.f;
            #pragma unroll
            for (int d = 0; d < 4; d++) acc += Q[h * 4 + d] * k_b[h * 4 + d];
            for (int dm = 0; dm < DM; dm++) acc += srow[dm] * sqk[h * DM + dm];
            g_sconst[bt * NH + h] = acc;
        }
    } else if (blk < 88) {
        const int d0 = (blk - 56) * 8;
        for (int k = 0; k < 8; k++) {
            int d = d0 + k;
            if (tid < 128) {
                int c = tid;
                float w = inconv_w[d * CC + c];
                float wp = in_w[c] * w;
                g_W4[(c >> 2) * 1024 + d * 4 + (c & 3)] = wp;
                srow[c] = wp;
                srow[128 + c] = in_b[c] * w;
            }
            __syncthreads();
            if (tid < 16) {
                float acc = 0.f;
                #pragma unroll
                for (int j = 0; j < 8; j++) acc += srow[tid * 8 + j];
                g_GWT[tid * DM + d] = acc;
            }
            if (tid == 0) {
                float acc = 0.f;
                for (int c = 0; c < CC; c++) acc += srow[128 + c];
                g_bW[d] = acc;
            }
            __syncthreads();
        }
    } else {
        // M8 repack: o-pair interleaved. [d4][q][k*2+r] = mlp_w[(2q+r)*DM + d4*4+k]
        const int o0 = (blk - 88) * 4;
        for (int idx = tid; idx < 4 * DM; idx += 256) {
            int oo = o0 + (idx >> 8), dm = idx & 255;
            g_M8[(dm >> 2) * 512 + (oo >> 1) * 8 + (dm & 3) * 2 + (oo & 1)] =
                mlp_w[oo * DM + dm];
        }
    }
}

// ---------------------------------------------------------------------------
// Main: 512 threads, 8 w positions per block, 2 CTAs/SM.
__global__ void __launch_bounds__(512, 2)
ltae_main(const float* __restrict__ x,
          const float* __restrict__ mlp_b,
          const float* __restrict__ ln_w, const float* __restrict__ ln_b,
          const float* __restrict__ on_w, const float* __restrict__ on_b,
          float* __restrict__ out) {
    extern __shared__ float sm[];
    float* Z    = sm + OFF_Z;
    float* PL   = sm + OFF_PL;
    float* PH   = sm + OFF_PH;   // quarters 0,1
    float* OB   = sm + OFF_OB;
    float* RS   = sm + OFF_RS;
    float* SC   = sm + OFF_SC;
    float* PH2  = sm + OFF_SC;   // quarters 2,3 (SC dead after P5)
    float* COLS = sm + OFF_SC;   // overlay, dead before scores written
    float* GS   = sm + OFF_GS;
    float* CR   = sm + OFF_CR;

    const int tid = threadIdx.x;
    const int blk = blockIdx.x;
    const int wblk = blk & 15;
    const int hrow = (blk >> 4) & 127;
    const int b = blk >> 11;
    const int w0 = wblk * 8;

    const float* xb = x + (size_t)b * TT * CC * HWP + (size_t)hrow * 128 + w0;

    // stage Rp (one float4 per thread)
    {
        int h = tid >> 5, c4 = tid & 31;
        *(float4*)&RS[h * ZROW + c4 * 4] =
            *(const float4*)&g_Rp[h * CC + c4 * 4];
    }

    // ---- Phase 1: scalar gather (sector-coalesced over w) + column partials
    const int s = tid & 7;
    const int lane64 = tid >> 3;
    {
        float s0 = 0.f, q0 = 0.f, s1 = 0.f, q1 = 0.f;
        float* zp = Z + s * SSTRIDE;
        #pragma unroll 4
        for (int k = 0; k < 40; k++) {
            int pair = lane64 + (k << 6);
            float val = __ldg(xb + (size_t)pair * HWP + s);
            zp[(pair >> 7) * ZROW + (pair & 127)] = val;
            if (k & 1) { s1 += val; q1 += val * val; }
            else       { s0 += val; q0 += val * val; }
        }
        *(float2*)&COLS[s * 260 + lane64 * 2] = mk2(s0, q0);
        *(float2*)&COLS[s * 260 + (lane64 + 64) * 2] = mk2(s1, q1);
    }
    __syncthreads();

    if (tid < 128) {
        int ss = tid >> 4, g = tid & 15;
        float sum = 0.f, sq = 0.f;
        #pragma unroll
        for (int j = 0; j < 8; j++) {
            float2 p = *(const float2*)&COLS[ss * 260 + (g * 8 + j) * 2];
            sum += p.x; sq += p.y;
        }
        float mu = sum * (1.f / 160.f);
        float var = sq * (1.f / 160.f) - mu * mu;
        float inv = rsqrtf(var + 1e-5f);
        GS[(ss * 16 + g) * 2]     = inv;
        GS[(ss * 16 + g) * 2 + 1] = mu * inv;
    }
    __syncthreads();

    if (tid < 128) {
        int ss = tid >> 4, h = tid & 15;
        float c = g_bR[h];
        #pragma unroll
        for (int g = 0; g < 16; g++)
            c -= GS[(ss * 16 + g) * 2 + 1] * g_G[h * 16 + g];
        CR[ss * 16 + h] = c;
    }
    __syncthreads();

    // ---- Phase 2: scores from RAW z, 4t x 2h register tile on 320 threads
    //      (10 warps), z reads 8-lane broadcast, inv folded
    if (tid < 320) {
        const int hq = tid & 7;          // 8 head-pairs
        const int tmp = tid >> 3;        // 0..39
        const int tq = tmp % 5;
        const int ss = tmp / 5;
        const int t0 = tq * 4;
        const float* zb = Z + ss * SSTRIDE + t0 * ZROW;
        const float* rb = RS + hq * 2 * ZROW;
        float2 acc[4][2];
        #pragma unroll
        for (int tt = 0; tt < 4; tt++)
            #pragma unroll
            for (int j = 0; j < 2; j++) acc[tt][j] = mk2(0.f, 0.f);
        #pragma unroll 4
        for (int c4 = 0; c4 < 32; c4++) {
            float inv = GS[(ss * 16 + (c4 >> 1)) * 2];
            float2 iv = mk2(inv, inv);
            float2 al[4], ah[4];
            #pragma unroll
            for (int tt = 0; tt < 4; tt++) {
                float4 a = *(const float4*)(zb + tt * ZROW + c4 * 4);
                al[tt] = mul2(mk2(a.x, a.y), iv);
                ah[tt] = mul2(mk2(a.z, a.w), iv);
            }
            #pragma unroll
            for (int j = 0; j < 2; j++) {
                float4 r = *(const float4*)(rb + j * ZROW + c4 * 4);
                float2 rl = mk2(r.x, r.y), rh = mk2(r.z, r.w);
                #pragma unroll
                for (int tt = 0; tt < 4; tt++) {
                    acc[tt][j] = fma2(al[tt], rl, acc[tt][j]);
                    acc[tt][j] = fma2(ah[tt], rh, acc[tt][j]);
                }
            }
        }
        #pragma unroll
        for (int tt = 0; tt < 4; tt++)
            #pragma unroll
            for (int j = 0; j < 2; j++) {
                int h = hq * 2 + j, t = t0 + tt;
                SC[ss * 320 + h * 20 + t] =
                    (acc[tt][j].x + acc[tt][j].y + CR[ss * 16 + h]
                     + g_sconst[(b * TT + t) * NH + h]) * 0.5f;
            }
    }
    __syncthreads();

    // ---- Phase 3: softmax with in-place transpose SC -> attn[s][t][h]
    {
        float att[TT];
        int ss = tid >> 4, h = tid & 15;
        if (tid < 128) {
            const float* sp = SC + ss * 320 + h * 20;
            float m = -1e30f;
            #pragma unroll
            for (int t = 0; t < TT; t++) m = fmaxf(m, sp[t]);
            float sumv = 0.f;
            #pragma unroll
            for (int t = 0; t < TT; t++) { att[t] = __expf(sp[t] - m); sumv += att[t]; }
            float r = 1.f / sumv;
            #pragma unroll
            for (int t = 0; t < TT; t++) att[t] *= r;
        }
        __syncthreads();
        if (tid < 128) {
            #pragma unroll
            for (int t = 0; t < TT; t++) SC[ss * 320 + t * 16 + h] = att[t];
        }
    }
    __syncthreads();

    // ---- Phase 4: A[s,h,c] = inv_g * sum_t attn * z_raw, overlay into Z
    //      thread = (ss 8, hh 2, cq 32): z as LDS.128, attn as 2x LDS.128
    {
        const int ss4 = tid >> 6;
        const int hh = (tid >> 5) & 1;
        const int cq = tid & 31;
        float2 acc[8][2];   // [h-in-half][c01, c23]
        #pragma unroll
        for (int hp = 0; hp < 8; hp++) {
            acc[hp][0] = mk2(0.f, 0.f);
            acc[hp][1] = mk2(0.f, 0.f);
        }
        const float* zp = Z + ss4 * SSTRIDE + cq * 4;
        const float* ap = SC + ss4 * 320 + hh * 8;
        #pragma unroll 4
        for (int t = 0; t < TT; t++) {
            float4 z4 = *(const float4*)(zp + t * ZROW);
            float4 A0 = *(const float4*)(ap + t * 16);
            float4 A1 = *(const float4*)(ap + t * 16 + 4);
            float2 z01 = mk2(z4.x, z4.y), z23 = mk2(z4.z, z4.w);
            float av[8] = {A0.x, A0.y, A0.z, A0.w, A1.x, A1.y, A1.z, A1.w};
            #pragma unroll
            for (int hp = 0; hp < 8; hp++) {
                float2 a2 = mk2(av[hp], av[hp]);
                acc[hp][0] = fma2(a2, z01, acc[hp][0]);
                acc[hp][1] = fma2(a2, z23, acc[hp][1]);
            }
        }
        float inv = GS[(ss4 * 16 + (cq >> 1)) * 2];
        float2 iv = mk2(inv, inv);
        __syncthreads();              // all raw-z reads complete before overlay
        #pragma unroll
        for (int hp = 0; hp < 8; hp++) {
            float2 a01 = mul2(acc[hp][0], iv);
            float2 a23 = mul2(acc[hp][1], iv);
            float4 w;
            w.x = a01.x; w.y = a01.y; w.z = a23.x; w.w = a23.y;
            *(float4*)(Z + ss4 * ASTRIDE + (hh * 8 + hp) * ZROW + cq * 4) = w;
        }
    }
    __syncthreads();

    // ---- Phase 5: pooled; 256 threads own d, single pass over 8 samples
    if (tid < 256) {
        const int d = tid;
        const int h = d >> 4;
        float2 acc2[8];
        #pragma unroll
        for (int j = 0; j < 8; j++) acc2[j] = mk2(0.f, 0.f);
        #pragma unroll 4
        for (int c4 = 0; c4 < 32; c4++) {
            float4 w = __ldg((const float4*)(g_W4 + c4 * 1024 + d * 4));
            float2 wl = mk2(w.x, w.y), wh = mk2(w.z, w.w);
            #pragma unroll
            for (int j = 0; j < 8; j++) {
                float4 a = *(const float4*)(Z + j * ASTRIDE + h * ZROW + c4 * 4);
                acc2[j] = fma2(mk2(a.x, a.y), wl, acc2[j]);
                acc2[j] = fma2(mk2(a.z, a.w), wh, acc2[j]);
            }
        }
        float p[8];
        float bw = __ldg(g_bW + d);
        #pragma unroll
        for (int j = 0; j < 8; j++) p[j] = acc2[j].x + acc2[j].y + bw;
        #pragma unroll
        for (int g = 0; g < 16; g++) {
            float gw = __ldg(g_GWT + g * 256 + d);
            #pragma unroll
            for (int j = 0; j < 8; j++)
                p[j] -= GS[(j * 16 + g) * 2 + 1] * gw;
        }
        const float* vc = g_vconst + b * TT * DM + d;
        #pragma unroll 4
        for (int t = 0; t < TT; t++) {
            float vv = __ldg(vc + t * DM);
            #pragma unroll
            for (int j = 0; j < 8; j++)
                p[j] += SC[j * 320 + t * 16 + h] * vv;
        }
        #pragma unroll
        for (int j = 0; j < 8; j++) PL[j * 256 + d] = p[j];
    }
    __syncthreads();

    // ---- Phase 6: MLP; 256 threads = (q 64 o-pairs, dq 4 d-quarters)
    if (tid < 256) {
        const int q = tid & 63;
        const int dq = tid >> 6;
        float2 acc[8];
        #pragma unroll
        for (int j = 0; j < 8; j++) acc[j] = mk2(0.f, 0.f);
        const int d4base = dq * 16;
        #pragma unroll 4
        for (int k = 0; k < 16; k++) {
            int d4 = d4base + k;
            float4 w0 = __ldg((const float4*)(g_M8 + d4 * 512 + q * 8));
            float4 w1 = __ldg((const float4*)(g_M8 + d4 * 512 + q * 8 + 4));
            #pragma unroll
            for (int j = 0; j < 8; j++) {
                float4 pq = *(const float4*)(PL + j * 256 + d4 * 4);
                acc[j] = fma2(mk2(pq.x, pq.x), mk2(w0.x, w0.y), acc[j]);
                acc[j] = fma2(mk2(pq.y, pq.y), mk2(w0.z, w0.w), acc[j]);
                acc[j] = fma2(mk2(pq.z, pq.z), mk2(w1.x, w1.y), acc[j]);
                acc[j] = fma2(mk2(pq.w, pq.w), mk2(w1.z, w1.w), acc[j]);
            }
        }
        float* phq = (dq < 2) ? (PH + dq * 1024) : (PH2 + (dq - 2) * 1024);
        #pragma unroll
        for (int j = 0; j < 8; j++)
            *(float2*)(phq + j * 128 + q * 2) = acc[j];
    }
    __syncthreads();

    // ---- Phase 7: combine 4 quarters + LN + GELU + GN + transpose (256 thr)
    if (tid < 256) {
        int ss = tid >> 5, lane = tid & 31;
        float4 a0 = *(const float4*)(PH + ss * 128 + lane * 4);
        float4 a1 = *(const float4*)(PH + 1024 + ss * 128 + lane * 4);
        float4 a2 = *(const float4*)(PH2 + ss * 128 + lane * 4);
        float4 a3 = *(const float4*)(PH2 + 1024 + ss * 128 + lane * 4);
        float4 bb = __ldg((const float4*)(mlp_b + lane * 4));
        float4 vq;
        vq.x = a0.x + a1.x + a2.x + a3.x + bb.x;
        vq.y = a0.y + a1.y + a2.y + a3.y + bb.y;
        vq.z = a0.z + a1.z + a2.z + a3.z + bb.z;
        vq.w = a0.w + a1.w + a2.w + a3.w + bb.w;
        float smv = vq.x + vq.y + vq.z + vq.w;
        float sqv = vq.x * vq.x + vq.y * vq.y + vq.z * vq.z + vq.w * vq.w;
        #pragma unroll
        for (int off = 16; off; off >>= 1) {
            smv += __shfl_xor_sync(0xffffffffu, smv, off);
            sqv += __shfl_xor_sync(0xffffffffu, sqv, off);
        }
        float mu = smv * (1.f / 128.f);
        float inv = rsqrtf(sqv * (1.f / 128.f) - mu * mu + 1e-5f);
        float g[4]; float vv[4] = {vq.x, vq.y, vq.z, vq.w};
        #pragma unroll
        for (int j = 0; j < 4; j++) {
            int o = lane * 4 + j;
            float u = (vv[j] - mu) * inv * ln_w[o] + ln_b[o];
            g[j] = 0.5f * u * (1.f + erff(u * 0.70710678118654752f));
        }
        float s4v = g[0] + g[1] + g[2] + g[3];
        float q4 = g[0] * g[0] + g[1] * g[1] + g[2] * g[2] + g[3] * g[3];
        float s8 = s4v + __shfl_xor_sync(0xffffffffu, s4v, 1);
        float q8 = q4 + __shfl_xor_sync(0xffffffffu, q4, 1);
        float mu2 = s8 * 0.125f;
        float inv2 = rsqrtf(q8 * 0.125f - mu2 * mu2 + 1e-5f);
        #pragma unroll
        for (int j = 0; j < 4; j++) {
            int o = lane * 4 + j;
            OB[o * 9 + ss] = (g[j] - mu2) * inv2 * on_w[o] + on_b[o];
        }
    }
    __syncthreads();

    // ---- coalesced store: 8*128 floats
    #pragma unroll
    for (int k = tid; k < 1024; k += 512) {
        int o = k >> 3, sw = k & 7;
        out[(((size_t)(b * 128 + o)) << 14) + hrow * 128 + w0 + sw] = OB[o * 9 + sw];
    }
}

// ---------------------------------------------------------------------------
extern "C" void kernel_launch(void* const* d_in, const int* in_sizes, int n_in,
                              void* d_out, int out_size) {
    const float* x        = (const float*)d_in[0];
    const int*   bpos     = (const int*)  d_in[1];
    const float* in_w     = (const float*)d_in[2];
    const float* in_b     = (const float*)d_in[3];
    const float* inconv_w = (const float*)d_in[4];
    const float* inconv_b = (const float*)d_in[5];
    const float* Q        = (const float*)d_in[6];
    const float* k_w      = (const float*)d_in[7];
    const float* k_b      = (const float*)d_in[8];
    const float* mlp_w    = (const float*)d_in[9];
    const float* mlp_b    = (const float*)d_in[10];
    const float* ln_w     = (const float*)d_in[11];
    const float* ln_b     = (const float*)d_in[12];
    const float* on_w     = (const float*)d_in[13];
    const float* on_b     = (const float*)d_in[14];
    float* out = (float*)d_out;

    cudaFuncSetAttribute(ltae_main, cudaFuncAttributeMaxDynamicSharedMemorySize,
                         SMEM_BYTES);

    ltae_setup<<<120, 256>>>(bpos, in_w, in_b, inconv_w, inconv_b, Q, k_w, k_b,
                             mlp_w);
    ltae_main<<<4096, 512, SMEM_BYTES>>>(x, mlp_b, ln_w, ln_b, on_w, on_b, out);
}

// round 16
// speedup vs baseline: 1.0905x; 1.0236x over previous
#include <cuda_runtime.h>
#include <math.h>

#define TT 20
#define CC 128
#define DM 256
#define NH 16
#define HWP 16384
#define ZROW 132
#define SSTRIDE 2644
#define ASTRIDE 2112

// smem offsets (floats) — 8 samples, tight overlays
#define OFF_Z   0          // raw z; A overlays [0,16896)
#define OFF_PL  16896
#define OFF_PH  18944      // MLP partial quarters 0,1
#define OFF_OB  16896      // reuses PL after phase 6
#define OFF_RS  21152
#define OFF_SC  23264      // COLS overlay pre-P2; scores->attn; PH quarters 2,3 in P6
#define OFF_GS  25824
#define OFF_CR  26080
#define SMEM_FLOATS 26208
#define SMEM_BYTES (SMEM_FLOATS * 4)

__device__ float g_Rp[NH * CC];
__device__ float g_G[NH * NH];
__device__ float g_bR[NH];
__device__ float g_W4[DM * CC];      // [c4][d][j]
__device__ float g_GWT[NH * DM];     // [g][d]
__device__ float g_bW[DM];
__device__ float g_M8[DM * CC];      // [d4][q][k*2+r] : o-pair interleaved
__device__ float g_vconst[2 * TT * DM];
__device__ float g_sconst[2 * TT * NH];

union F2U { float2 f; unsigned long long u; };

__device__ __forceinline__ float2 fma2(float2 a, float2 b, float2 c) {
    F2U ua, ub, uc, ud;
    ua.f = a; ub.f = b; uc.f = c;
    asm("fma.rn.f32x2 %0, %1, %2, %3;"
        : "=l"(ud.u) : "l"(ua.u), "l"(ub.u), "l"(uc.u));
    return ud.f;
}
__device__ __forceinline__ float2 mul2(float2 a, float2 b) {
    F2U ua, ub, ud;
    ua.f = a; ub.f = b;
    asm("mul.rn.f32x2 %0, %1, %2;" : "=l"(ud.u) : "l"(ua.u), "l"(ub.u));
    return ud.f;
}
__device__ __forceinline__ float2 mk2(float a, float b) {
    float2 r; r.x = a; r.y = b; return r;
}

// ---------------------------------------------------------------------------
// Setup (grid 120, 256 thr)
__global__ void ltae_setup(const int* __restrict__ bpos,
                           const float* __restrict__ in_w,
                           const float* __restrict__ in_b,
                           const float* __restrict__ inconv_w,
                           const float* __restrict__ inconv_b,
                           const float* __restrict__ Q,
                           const float* __restrict__ k_w,
                           const float* __restrict__ k_b,
                           const float* __restrict__ mlp_w) {
    __shared__ float sqk[NH * DM];
    __shared__ float srow[2 * DM];
    const int tid = threadIdx.x;
    const int blk = blockIdx.x;

    for (int i = tid; i < NH * DM; i += 256) {
        int h = i >> 8, dm = i & 255;
        float acc = 0.f;
        #pragma unroll
        for (int d = 0; d < 4; d++) acc += Q[h * 4 + d] * k_w[(h * 4 + d) * DM + dm];
        sqk[i] = acc;
    }
    __syncthreads();

    if (blk < 16) {
        const int h = blk;
        if (tid < 128) {
            int c = tid;
            float acc = 0.f;
            for (int dm = 0; dm < DM; dm++)
                acc += sqk[h * DM + dm] * inconv_w[dm * CC + c];
            srow[c] = acc;
            g_Rp[h * CC + c] = in_w[c] * acc;
        }
        __syncthreads();
        if (tid < 16) {
            float acc = 0.f;
            #pragma unroll
            for (int j = 0; j < 8; j++) {
                int c = tid * 8 + j;
                acc += in_w[c] * srow[c];
            }
            g_G[h * 16 + tid] = acc;
        }
        if (tid == 0) {
            float acc = 0.f;
            for (int c = 0; c < CC; c++) acc += in_b[c] * srow[c];
            g_bR[h] = acc;
        }
    } else if (blk < 56) {
        const int bt = blk - 16;
        {
            int dm = tid;
            int ii = dm & 15;
            // denom = 1000^( (2*(ii/2)) / 16 )  computed in f32 (MUFU path)
            float ex = (float)(ii & ~1) * (1.0f / 16.0f);
            float denom = exp2f(ex * 9.96578428466209f);   // log2(1000)
            float tab = (float)bpos[bt] / denom;
            float pe = (ii & 1) ? cosf(tab) : sinf(tab);
            float vv = inconv_b[dm] + pe;
            g_vconst[bt * DM + dm] = vv;
            srow[dm] = vv;
        }
        __syncthreads();
        if (tid < 16) {
            int h = tid;
            float acc = 0.f;
            #pragma unroll
            for (int d = 0; d < 4; d++) acc += Q[h * 4 + d] * k_b[h * 4 + d];
            for (int dm = 0; dm < DM; dm++) acc += srow[dm] * sqk[h * DM + dm];
            g_sconst[bt * NH + h] = acc;
        }
    } else if (blk < 88) {
        const int d0 = (blk - 56) * 8;
        for (int k = 0; k < 8; k++) {
            int d = d0 + k;
            if (tid < 128) {
                int c = tid;
                float w = inconv_w[d * CC + c];
                float wp = in_w[c] * w;
                g_W4[(c >> 2) * 1024 + d * 4 + (c & 3)] = wp;
                srow[c] = wp;
                srow[128 + c] = in_b[c] * w;
            }
            __syncthreads();
            if (tid < 16) {
                float acc = 0.f;
                #pragma unroll
                for (int j = 0; j < 8; j++) acc += srow[tid * 8 + j];
                g_GWT[tid * DM + d] = acc;
            }
            if (tid == 0) {
                float acc = 0.f;
                for (int c = 0; c < CC; c++) acc += srow[128 + c];
                g_bW[d] = acc;
            }
            __syncthreads();
        }
    } else {
        // M8 repack: o-pair interleaved. [d4][q][k*2+r] = mlp_w[(2q+r)*DM + d4*4+k]
        const int o0 = (blk - 88) * 4;
        for (int idx = tid; idx < 4 * DM; idx += 256) {
            int oo = o0 + (idx >> 8), dm = idx & 255;
            g_M8[(dm >> 2) * 512 + (oo >> 1) * 8 + (dm & 3) * 2 + (oo & 1)] =
                mlp_w[oo * DM + dm];
        }
    }
}

// ---------------------------------------------------------------------------
// Main: 512 threads, 8 w positions per block, 2 CTAs/SM.
__global__ void __launch_bounds__(512, 2)
ltae_main(const float* __restrict__ x,
          const float* __restrict__ mlp_b,
          const float* __restrict__ ln_w, const float* __restrict__ ln_b,
          const float* __restrict__ on_w, const float* __restrict__ on_b,
          float* __restrict__ out) {
    extern __shared__ float sm[];
    float* Z    = sm + OFF_Z;
    float* PL   = sm + OFF_PL;
    float* PH   = sm + OFF_PH;   // quarters 0,1
    float* OB   = sm + OFF_OB;
    float* RS   = sm + OFF_RS;
    float* SC   = sm + OFF_SC;
    float* PH2  = sm + OFF_SC;   // quarters 2,3 (SC dead after P5)
    float* COLS = sm + OFF_SC;   // overlay, dead before scores written
    float* GS   = sm + OFF_GS;
    float* CR   = sm + OFF_CR;

    const int tid = threadIdx.x;
    const int blk = blockIdx.x;
    const int wblk = blk & 15;
    const int hrow = (blk >> 4) & 127;
    const int b = blk >> 11;
    const int w0 = wblk * 8;

    const float* xb = x + (size_t)b * TT * CC * HWP + (size_t)hrow * 128 + w0;

    // stage Rp (one float4 per thread)
    {
        int h = tid >> 5, c4 = tid & 31;
        *(float4*)&RS[h * ZROW + c4 * 4] =
            *(const float4*)&g_Rp[h * CC + c4 * 4];
    }

    // ---- Phase 1: scalar gather (sector-coalesced over w) + column partials
    const int s = tid & 7;
    const int lane64 = tid >> 3;
    {
        float s0 = 0.f, q0 = 0.f, s1 = 0.f, q1 = 0.f;
        float* zp = Z + s * SSTRIDE;
        #pragma unroll 4
        for (int k = 0; k < 40; k++) {
            int pair = lane64 + (k << 6);
            float val = __ldg(xb + (size_t)pair * HWP + s);
            zp[(pair >> 7) * ZROW + (pair & 127)] = val;
            if (k & 1) { s1 += val; q1 += val * val; }
            else       { s0 += val; q0 += val * val; }
        }
        *(float2*)&COLS[s * 260 + lane64 * 2] = mk2(s0, q0);
        *(float2*)&COLS[s * 260 + (lane64 + 64) * 2] = mk2(s1, q1);
    }
    __syncthreads();

    if (tid < 128) {
        int ss = tid >> 4, g = tid & 15;
        float sum = 0.f, sq = 0.f;
        #pragma unroll
        for (int j = 0; j < 8; j++) {
            float2 p = *(const float2*)&COLS[ss * 260 + (g * 8 + j) * 2];
            sum += p.x; sq += p.y;
        }
        float mu = sum * (1.f / 160.f);
        float var = sq * (1.f / 160.f) - mu * mu;
        float inv = rsqrtf(var + 1e-5f);
        GS[(ss * 16 + g) * 2]     = inv;
        GS[(ss * 16 + g) * 2 + 1] = mu * inv;
    }
    __syncthreads();

    if (tid < 128) {
        int ss = tid >> 4, h = tid & 15;
        float c = g_bR[h];
        #pragma unroll
        for (int g = 0; g < 16; g++)
            c -= GS[(ss * 16 + g) * 2 + 1] * g_G[h * 16 + g];
        CR[ss * 16 + h] = c;
    }
    __syncthreads();

    // ---- Phase 2: scores from RAW z, 4t x 2h register tile on 320 threads
    if (tid < 320) {
        const int hq = tid & 7;          // 8 head-pairs
        const int tmp = tid >> 3;        // 0..39
        const int tq = tmp % 5;
        const int ss = tmp / 5;
        const int t0 = tq * 4;
        const float* zb = Z + ss * SSTRIDE + t0 * ZROW;
        const float* rb = RS + hq * 2 * ZROW;
        float2 acc[4][2];
        #pragma unroll
        for (int tt = 0; tt < 4; tt++)
            #pragma unroll
            for (int j = 0; j < 2; j++) acc[tt][j] = mk2(0.f, 0.f);
        #pragma unroll 4
        for (int c4 = 0; c4 < 32; c4++) {
            float inv = GS[(ss * 16 + (c4 >> 1)) * 2];
            float2 iv = mk2(inv, inv);
            float2 al[4], ah[4];
            #pragma unroll
            for (int tt = 0; tt < 4; tt++) {
                float4 a = *(const float4*)(zb + tt * ZROW + c4 * 4);
                al[tt] = mul2(mk2(a.x, a.y), iv);
                ah[tt] = mul2(mk2(a.z, a.w), iv);
            }
            #pragma unroll
            for (int j = 0; j < 2; j++) {
                float4 r = *(const float4*)(rb + j * ZROW + c4 * 4);
                float2 rl = mk2(r.x, r.y), rh = mk2(r.z, r.w);
                #pragma unroll
                for (int tt = 0; tt < 4; tt++) {
                    acc[tt][j] = fma2(al[tt], rl, acc[tt][j]);
                    acc[tt][j] = fma2(ah[tt], rh, acc[tt][j]);
                }
            }
        }
        #pragma unroll
        for (int tt = 0; tt < 4; tt++)
            #pragma unroll
            for (int j = 0; j < 2; j++) {
                int h = hq * 2 + j, t = t0 + tt;
                SC[ss * 320 + h * 20 + t] =
                    (acc[tt][j].x + acc[tt][j].y + CR[ss * 16 + h]
                     + g_sconst[(b * TT + t) * NH + h]) * 0.5f;
            }
    }
    __syncthreads();

    // ---- Phase 3: softmax with in-place transpose SC -> attn[s][t][h]
    {
        float att[TT];
        int ss = tid >> 4, h = tid & 15;
        if (tid < 128) {
            const float* sp = SC + ss * 320 + h * 20;
            float m = -1e30f;
            #pragma unroll
            for (int t = 0; t < TT; t++) m = fmaxf(m, sp[t]);
            float sumv = 0.f;
            #pragma unroll
            for (int t = 0; t < TT; t++) { att[t] = __expf(sp[t] - m); sumv += att[t]; }
            float r = 1.f / sumv;
            #pragma unroll
            for (int t = 0; t < TT; t++) att[t] *= r;
        }
        __syncthreads();
        if (tid < 128) {
            #pragma unroll
            for (int t = 0; t < TT; t++) SC[ss * 320 + t * 16 + h] = att[t];
        }
    }
    __syncthreads();

    // ---- Phase 4: A[s,h,c] = inv_g * sum_t attn * z_raw, overlay into Z
    //      thread = (ss 8, hh 2, cq 32): z as LDS.128, attn as 2x LDS.128
    {
        const int ss4 = tid >> 6;
        const int hh = (tid >> 5) & 1;
        const int cq = tid & 31;
        float2 acc[8][2];   // [h-in-half][c01, c23]
        #pragma unroll
        for (int hp = 0; hp < 8; hp++) {
            acc[hp][0] = mk2(0.f, 0.f);
            acc[hp][1] = mk2(0.f, 0.f);
        }
        const float* zp = Z + ss4 * SSTRIDE + cq * 4;
        const float* ap = SC + ss4 * 320 + hh * 8;
        #pragma unroll 4
        for (int t = 0; t < TT; t++) {
            float4 z4 = *(const float4*)(zp + t * ZROW);
            float4 A0 = *(const float4*)(ap + t * 16);
            float4 A1 = *(const float4*)(ap + t * 16 + 4);
            float2 z01 = mk2(z4.x, z4.y), z23 = mk2(z4.z, z4.w);
            float av[8] = {A0.x, A0.y, A0.z, A0.w, A1.x, A1.y, A1.z, A1.w};
            #pragma unroll
            for (int hp = 0; hp < 8; hp++) {
                float2 a2 = mk2(av[hp], av[hp]);
                acc[hp][0] = fma2(a2, z01, acc[hp][0]);
                acc[hp][1] = fma2(a2, z23, acc[hp][1]);
            }
        }
        float inv = GS[(ss4 * 16 + (cq >> 1)) * 2];
        float2 iv = mk2(inv, inv);
        __syncthreads();              // all raw-z reads complete before overlay
        #pragma unroll
        for (int hp = 0; hp < 8; hp++) {
            float2 a01 = mul2(acc[hp][0], iv);
            float2 a23 = mul2(acc[hp][1], iv);
            float4 w;
            w.x = a01.x; w.y = a01.y; w.z = a23.x; w.w = a23.y;
            *(float4*)(Z + ss4 * ASTRIDE + (hh * 8 + hp) * ZROW + cq * 4) = w;
        }
    }
    __syncthreads();

    // ---- Phase 5: pooled; 512 threads = (d 256, sample-half 2), 4 samples each
    {
        const int d = tid & 255;
        const int sh = tid >> 8;          // 0..1 -> samples sh*4..sh*4+3
        const int h = d >> 4;
        float2 acc2[4];
        #pragma unroll
        for (int j = 0; j < 4; j++) acc2[j] = mk2(0.f, 0.f);
        #pragma unroll 4
        for (int c4 = 0; c4 < 32; c4++) {
            float4 w = __ldg((const float4*)(g_W4 + c4 * 1024 + d * 4));
            float2 wl = mk2(w.x, w.y), wh = mk2(w.z, w.w);
            #pragma unroll
            for (int j = 0; j < 4; j++) {
                float4 a = *(const float4*)(Z + (sh * 4 + j) * ASTRIDE + h * ZROW + c4 * 4);
                acc2[j] = fma2(mk2(a.x, a.y), wl, acc2[j]);
                acc2[j] = fma2(mk2(a.z, a.w), wh, acc2[j]);
            }
        }
        float p[4];
        float bw = __ldg(g_bW + d);
        #pragma unroll
        for (int j = 0; j < 4; j++) p[j] = acc2[j].x + acc2[j].y + bw;
        #pragma unroll
        for (int g = 0; g < 16; g++) {
            float gw = __ldg(g_GWT + g * 256 + d);
            #pragma unroll
            for (int j = 0; j < 4; j++)
                p[j] -= GS[((sh * 4 + j) * 16 + g) * 2 + 1] * gw;
        }
        const float* vc = g_vconst + b * TT * DM + d;
        #pragma unroll 4
        for (int t = 0; t < TT; t++) {
            float vv = __ldg(vc + t * DM);
            #pragma unroll
            for (int j = 0; j < 4; j++)
                p[j] += SC[(sh * 4 + j) * 320 + t * 16 + h] * vv;
        }
        #pragma unroll
        for (int j = 0; j < 4; j++) PL[(sh * 4 + j) * 256 + d] = p[j];
    }
    __syncthreads();

    // ---- Phase 6: MLP; 256 threads = (q 64 o-pairs, dq 4 d-quarters)
    if (tid < 256) {
        const int q = tid & 63;
        const int dq = tid >> 6;
        float2 acc[8];
        #pragma unroll
        for (int j = 0; j < 8; j++) acc[j] = mk2(0.f, 0.f);
        const int d4base = dq * 16;
        #pragma unroll 4
        for (int k = 0; k < 16; k++) {
            int d4 = d4base + k;
            float4 w0 = __ldg((const float4*)(g_M8 + d4 * 512 + q * 8));
            float4 w1 = __ldg((const float4*)(g_M8 + d4 * 512 + q * 8 + 4));
            #pragma unroll
            for (int j = 0; j < 8; j++) {
                float4 pq = *(const float4*)(PL + j * 256 + d4 * 4);
                acc[j] = fma2(mk2(pq.x, pq.x), mk2(w0.x, w0.y), acc[j]);
                acc[j] = fma2(mk2(pq.y, pq.y), mk2(w0.z, w0.w), acc[j]);
                acc[j] = fma2(mk2(pq.z, pq.z), mk2(w1.x, w1.y), acc[j]);
                acc[j] = fma2(mk2(pq.w, pq.w), mk2(w1.z, w1.w), acc[j]);
            }
        }
        float* phq = (dq < 2) ? (PH + dq * 1024) : (PH2 + (dq - 2) * 1024);
        #pragma unroll
        for (int j = 0; j < 8; j++)
            *(float2*)(phq + j * 128 + q * 2) = acc[j];
    }
    __syncthreads();

    // ---- Phase 7: combine 4 quarters + LN + GELU + GN + transpose (256 thr)
    if (tid < 256) {
        int ss = tid >> 5, lane = tid & 31;
        float4 a0 = *(const float4*)(PH + ss * 128 + lane * 4);
        float4 a1 = *(const float4*)(PH + 1024 + ss * 128 + lane * 4);
        float4 a2 = *(const float4*)(PH2 + ss * 128 + lane * 4);
        float4 a3 = *(const float4*)(PH2 + 1024 + ss * 128 + lane * 4);
        float4 bb = __ldg((const float4*)(mlp_b + lane * 4));
        float4 vq;
        vq.x = a0.x + a1.x + a2.x + a3.x + bb.x;
        vq.y = a0.y + a1.y + a2.y + a3.y + bb.y;
        vq.z = a0.z + a1.z + a2.z + a3.z + bb.z;
        vq.w = a0.w + a1.w + a2.w + a3.w + bb.w;
        float smv = vq.x + vq.y + vq.z + vq.w;
        float sqv = vq.x * vq.x + vq.y * vq.y + vq.z * vq.z + vq.w * vq.w;
        #pragma unroll
        for (int off = 16; off; off >>= 1) {
            smv += __shfl_xor_sync(0xffffffffu, smv, off);
            sqv += __shfl_xor_sync(0xffffffffu, sqv, off);
        }
        float mu = smv * (1.f / 128.f);
        float inv = rsqrtf(sqv * (1.f / 128.f) - mu * mu + 1e-5f);
        float g[4]; float vv[4] = {vq.x, vq.y, vq.z, vq.w};
        #pragma unroll
        for (int j = 0; j < 4; j++) {
            int o = lane * 4 + j;
            float u = (vv[j] - mu) * inv * ln_w[o] + ln_b[o];
            g[j] = 0.5f * u * (1.f + erff(u * 0.70710678118654752f));
        }
        float s4v = g[0] + g[1] + g[2] + g[3];
        float q4 = g[0] * g[0] + g[1] * g[1] + g[2] * g[2] + g[3] * g[3];
        float s8 = s4v + __shfl_xor_sync(0xffffffffu, s4v, 1);
        float q8 = q4 + __shfl_xor_sync(0xffffffffu, q4, 1);
        float mu2 = s8 * 0.125f;
        float inv2 = rsqrtf(q8 * 0.125f - mu2 * mu2 + 1e-5f);
        #pragma unroll
        for (int j = 0; j < 4; j++) {
            int o = lane * 4 + j;
            OB[o * 9 + ss] = (g[j] - mu2) * inv2 * on_w[o] + on_b[o];
        }
    }
    __syncthreads();

    // ---- coalesced store: 8*128 floats
    #pragma unroll
    for (int k = tid; k < 1024; k += 512) {
        int o = k >> 3, sw = k & 7;
        out[(((size_t)(b * 128 + o)) << 14) + hrow * 128 + w0 + sw] = OB[o * 9 + sw];
    }
}

// ---------------------------------------------------------------------------
extern "C" void kernel_launch(void* const* d_in, const int* in_sizes, int n_in,
                              void* d_out, int out_size) {
    const float* x        = (const float*)d_in[0];
    const int*   bpos     = (const int*)  d_in[1];
    const float* in_w     = (const float*)d_in[2];
    const float* in_b     = (const float*)d_in[3];
    const float* inconv_w = (const float*)d_in[4];
    const float* inconv_b = (const float*)d_in[5];
    const float* Q        = (const float*)d_in[6];
    const float* k_w      = (const float*)d_in[7];
    const float* k_b      = (const float*)d_in[8];
    const float* mlp_w    = (const float*)d_in[9];
    const float* mlp_b    = (const float*)d_in[10];
    const float* ln_w     = (const float*)d_in[11];
    const float* ln_b     = (const float*)d_in[12];
    const float* on_w     = (const float*)d_in[13];
    const float* on_b     = (const float*)d_in[14];
    float* out = (float*)d_out;

    cudaFuncSetAttribute(ltae_main, cudaFuncAttributeMaxDynamicSharedMemorySize,
                         SMEM_BYTES);

    ltae_setup<<<120, 256>>>(bpos, in_w, in_b, inconv_w, inconv_b, Q, k_w, k_b,
                             mlp_w);
    ltae_main<<<4096, 512, SMEM_BYTES>>>(x, mlp_b, ln_w, ln_b, on_w, on_b, out);
}